// round 1
// baseline (speedup 1.0000x reference)
#include <cuda_runtime.h>
#include <math.h>
#include <stdint.h>

#define NB 4
#define NT 8192
#define NC 64
#define NS 256
#define NV 256
#define NL 30
#define NTOK (NB*NT)
#define KC (2*NC)       /* 128 */
#define KSKIP (NL*NC)   /* 1920 */

// ---- device scratch (no allocations allowed) ----
__device__ float g_xa[NTOK*NC];
__device__ float g_xb[NTOK*NC];
__device__ float g_gates[(size_t)NTOK*KSKIP];   // [tok][l*64+c], ~252 MB
__device__ float g_skipb[NS];
__device__ float g_num;

// ---------------- prep: sum skip biases, zero loss accumulator --------------
__global__ void prep_kernel(const float* __restrict__ skip_b) {
    int s = threadIdx.x;
    float a = 0.f;
    #pragma unroll 6
    for (int l = 0; l < NL; l++) a += skip_b[l*NS + s];
    g_skipb[s] = a;
    if (s == 0) g_num = 0.f;
}

// ---------------- embedding of right-shifted labels --------------------------
__global__ void embed_kernel(const int* __restrict__ wf, const float* __restrict__ emb) {
    int tid = threadIdx.x;
    int tok = blockIdx.x*4 + (tid >> 6);
    int c   = tid & 63;
    int t   = tok & (NT-1);
    int lab = (t == 0) ? 128 : wf[tok-1];
    g_xa[tok*NC + c] = emb[lab*NC + c];
}

// ---------------- one WaveNet layer ------------------------------------------
// 64 tokens/CTA. warp owns 8 tokens, lane owns 4 conv-out cols (of 128).
__global__ __launch_bounds__(256, 1) void layer_kernel(
    const float* __restrict__ conv_w, const float* __restrict__ conv_b,
    const float* __restrict__ res_w,  const float* __restrict__ res_b,
    int l, int d, int flip)
{
    const float* __restrict__ xin  = flip ? g_xb : g_xa;
    float* __restrict__       xout = flip ? g_xa : g_xb;

    extern __shared__ float sm[];
    float* sW = sm;                 // [128][128] concat conv weights
    float* sX = sW + KC*KC;         // [128][64]  xcat transposed (k-major)
    float* sR = sX + KC*64;         // [64][64]   res weights
    float* sH = sR + NC*NC;         // [64][128]  pre-activation
    float* sG = sH + 64*KC;         // [64][64]   gate

    const int tid  = threadIdx.x;
    const int tok0 = blockIdx.x * 64;

    // stage weights: k<64 pairs with x[t] (conv_w[l,1]); k>=64 with x[t-d] (conv_w[l,0])
    for (int idx = tid; idx < KC*KC; idx += 256) {
        int k = idx >> 7, f = idx & 127;
        sW[idx] = (k < NC) ? conv_w[((l*2+1)*NC + k)*KC + f]
                           : conv_w[((l*2+0)*NC + (k-NC))*KC + f];
    }
    for (int idx = tid; idx < NC*NC; idx += 256)
        sR[idx] = res_w[l*NC*NC + idx];
    // gather-transposed activation tile: sX[k][j]
    for (int idx = tid; idx < KC*64; idx += 256) {
        int k = idx >> 6, j = idx & 63;
        int tok = tok0 + j;
        float v;
        if (k < NC) v = xin[tok*NC + k];
        else {
            int t = tok & (NT-1);
            v = (t >= d) ? xin[(tok-d)*NC + (k-NC)] : 0.f;
        }
        sX[idx] = v;
    }
    __syncthreads();

    const int warp = tid >> 5, lane = tid & 31;

    // conv GEMM: h = xcat @ Wcat + b   (M=64 tok, N=128, K=128)
    float acc[8][4];
    {
        float4 cb = *(const float4*)&conv_b[l*KC + lane*4];
        #pragma unroll
        for (int jj = 0; jj < 8; jj++) {
            acc[jj][0]=cb.x; acc[jj][1]=cb.y; acc[jj][2]=cb.z; acc[jj][3]=cb.w;
        }
    }
    #pragma unroll 4
    for (int k = 0; k < KC; k++) {
        float4 w  = *(const float4*)&sW[k*KC + lane*4];
        float4 a0 = *(const float4*)&sX[k*64 + warp*8];
        float4 a1 = *(const float4*)&sX[k*64 + warp*8 + 4];
        float a[8] = {a0.x,a0.y,a0.z,a0.w,a1.x,a1.y,a1.z,a1.w};
        #pragma unroll
        for (int jj = 0; jj < 8; jj++) {
            acc[jj][0] += a[jj]*w.x;
            acc[jj][1] += a[jj]*w.y;
            acc[jj][2] += a[jj]*w.z;
            acc[jj][3] += a[jj]*w.w;
        }
    }
    #pragma unroll
    for (int jj = 0; jj < 8; jj++) {
        float4 v = make_float4(acc[jj][0],acc[jj][1],acc[jj][2],acc[jj][3]);
        *(float4*)&sH[(warp*8+jj)*KC + lane*4] = v;
    }
    __syncthreads();

    // gate = tanh(h[:64]) * sigmoid(h[64:]); write to smem + global gates
    #pragma unroll
    for (int jj = 0; jj < 8; jj++) {
        int tk = warp*8 + jj;
        #pragma unroll
        for (int cc = 0; cc < 2; cc++) {
            int c = lane + 32*cc;
            float h1 = sH[tk*KC + c];
            float h2 = sH[tk*KC + NC + c];
            float g  = tanhf(h1) * (1.f / (1.f + expf(-h2)));
            sG[tk*NC + c] = g;
            g_gates[(size_t)(tok0+tk)*KSKIP + l*NC + c] = g;
        }
    }
    __syncthreads();

    // residual GEMM: xout = xin + gate @ res_w + res_b  (N=64, K=64)
    float acc2[8][2];
    {
        float r0 = res_b[l*NC + lane];
        float r1 = res_b[l*NC + lane + 32];
        #pragma unroll
        for (int jj = 0; jj < 8; jj++) { acc2[jj][0]=r0; acc2[jj][1]=r1; }
    }
    #pragma unroll 2
    for (int c4 = 0; c4 < 16; c4++) {
        float wA[4], wB[4];
        #pragma unroll
        for (int cc = 0; cc < 4; cc++) {
            wA[cc] = sR[(c4*4+cc)*NC + lane];
            wB[cc] = sR[(c4*4+cc)*NC + lane + 32];
        }
        #pragma unroll
        for (int jj = 0; jj < 8; jj++) {
            float4 gv = *(const float4*)&sG[(warp*8+jj)*NC + c4*4];
            acc2[jj][0] += gv.x*wA[0] + gv.y*wA[1] + gv.z*wA[2] + gv.w*wA[3];
            acc2[jj][1] += gv.x*wB[0] + gv.y*wB[1] + gv.z*wB[2] + gv.w*wB[3];
        }
    }
    #pragma unroll
    for (int jj = 0; jj < 8; jj++) {
        int tok = tok0 + warp*8 + jj;
        xout[tok*NC + lane]      = xin[tok*NC + lane]      + acc2[jj][0];
        xout[tok*NC + lane + 32] = xin[tok*NC + lane + 32] + acc2[jj][1];
    }
}

// ---------------- head helper: 64x256 <- 64x256 @ 256x256 (+bias, opt relu) --
__device__ __forceinline__ void gemm256(const float* sIn, const float* __restrict__ W,
                                        const float* __restrict__ bias, float* sOut,
                                        int warp, int lane, bool do_relu)
{
    float acc[8][8];
    {
        float4 bv0 = *(const float4*)&bias[lane*8];
        float4 bv1 = *(const float4*)&bias[lane*8 + 4];
        #pragma unroll
        for (int jj = 0; jj < 8; jj++) {
            acc[jj][0]=bv0.x; acc[jj][1]=bv0.y; acc[jj][2]=bv0.z; acc[jj][3]=bv0.w;
            acc[jj][4]=bv1.x; acc[jj][5]=bv1.y; acc[jj][6]=bv1.z; acc[jj][7]=bv1.w;
        }
    }
    for (int k = 0; k < 256; k += 4) {
        float a[8][4];
        #pragma unroll
        for (int jj = 0; jj < 8; jj++) {
            float4 v = *(const float4*)&sIn[(warp*8+jj)*256 + k];
            a[jj][0]=v.x; a[jj][1]=v.y; a[jj][2]=v.z; a[jj][3]=v.w;
        }
        #pragma unroll
        for (int cc = 0; cc < 4; cc++) {
            float4 u0 = *(const float4*)&W[(k+cc)*256 + lane*8];
            float4 u1 = *(const float4*)&W[(k+cc)*256 + lane*8 + 4];
            #pragma unroll
            for (int jj = 0; jj < 8; jj++) {
                acc[jj][0]+=a[jj][cc]*u0.x; acc[jj][1]+=a[jj][cc]*u0.y;
                acc[jj][2]+=a[jj][cc]*u0.z; acc[jj][3]+=a[jj][cc]*u0.w;
                acc[jj][4]+=a[jj][cc]*u1.x; acc[jj][5]+=a[jj][cc]*u1.y;
                acc[jj][6]+=a[jj][cc]*u1.z; acc[jj][7]+=a[jj][cc]*u1.w;
            }
        }
    }
    #pragma unroll
    for (int jj = 0; jj < 8; jj++) {
        float4 o0, o1;
        o0.x=acc[jj][0]; o0.y=acc[jj][1]; o0.z=acc[jj][2]; o0.w=acc[jj][3];
        o1.x=acc[jj][4]; o1.y=acc[jj][5]; o1.z=acc[jj][6]; o1.w=acc[jj][7];
        if (do_relu) {
            o0.x=fmaxf(o0.x,0.f); o0.y=fmaxf(o0.y,0.f); o0.z=fmaxf(o0.z,0.f); o0.w=fmaxf(o0.w,0.f);
            o1.x=fmaxf(o1.x,0.f); o1.y=fmaxf(o1.y,0.f); o1.z=fmaxf(o1.z,0.f); o1.w=fmaxf(o1.w,0.f);
        }
        *(float4*)&sOut[(warp*8+jj)*256 + lane*8]     = o0;
        *(float4*)&sOut[(warp*8+jj)*256 + lane*8 + 4] = o1;
    }
}

// ---------------- head: skip GEMM(K=1920) + w0/relu + w1 + CE ----------------
__global__ __launch_bounds__(256, 1) void head_kernel(
    const float* __restrict__ skip_w,
    const float* __restrict__ w0, const float* __restrict__ b0,
    const float* __restrict__ w1, const float* __restrict__ b1,
    const int* __restrict__ wf, const int* __restrict__ lens)
{
    extern __shared__ float sm[];
    float* sA   = sm;              // 64x256: skip_sum, then logits
    float* sHid = sm + 64*256;     // 64x256

    const int tid = threadIdx.x, warp = tid >> 5, lane = tid & 31;
    const int tok0 = blockIdx.x * 64;

    // phase 1: skip_sum = gates @ skip_w + sum(skip_b)    (K = 1920)
    float acc[8][8];
    {
        float4 bv0 = *(const float4*)&g_skipb[lane*8];
        float4 bv1 = *(const float4*)&g_skipb[lane*8 + 4];
        #pragma unroll
        for (int jj = 0; jj < 8; jj++) {
            acc[jj][0]=bv0.x; acc[jj][1]=bv0.y; acc[jj][2]=bv0.z; acc[jj][3]=bv0.w;
            acc[jj][4]=bv1.x; acc[jj][5]=bv1.y; acc[jj][6]=bv1.z; acc[jj][7]=bv1.w;
        }
    }
    for (int k = 0; k < KSKIP; k += 4) {
        float a[8][4];
        #pragma unroll
        for (int jj = 0; jj < 8; jj++) {
            float4 v = *(const float4*)(g_gates + (size_t)(tok0+warp*8+jj)*KSKIP + k);
            a[jj][0]=v.x; a[jj][1]=v.y; a[jj][2]=v.z; a[jj][3]=v.w;
        }
        #pragma unroll
        for (int cc = 0; cc < 4; cc++) {
            float4 u0 = *(const float4*)&skip_w[(k+cc)*NS + lane*8];
            float4 u1 = *(const float4*)&skip_w[(k+cc)*NS + lane*8 + 4];
            #pragma unroll
            for (int jj = 0; jj < 8; jj++) {
                acc[jj][0]+=a[jj][cc]*u0.x; acc[jj][1]+=a[jj][cc]*u0.y;
                acc[jj][2]+=a[jj][cc]*u0.z; acc[jj][3]+=a[jj][cc]*u0.w;
                acc[jj][4]+=a[jj][cc]*u1.x; acc[jj][5]+=a[jj][cc]*u1.y;
                acc[jj][6]+=a[jj][cc]*u1.z; acc[jj][7]+=a[jj][cc]*u1.w;
            }
        }
    }
    #pragma unroll
    for (int jj = 0; jj < 8; jj++) {
        *(float4*)&sA[(warp*8+jj)*256 + lane*8]     = make_float4(acc[jj][0],acc[jj][1],acc[jj][2],acc[jj][3]);
        *(float4*)&sA[(warp*8+jj)*256 + lane*8 + 4] = make_float4(acc[jj][4],acc[jj][5],acc[jj][6],acc[jj][7]);
    }
    __syncthreads();

    // phase 2: hid0 = relu(skip @ w0 + b0)
    gemm256(sA, w0, b0, sHid, warp, lane, true);
    __syncthreads();
    // phase 3: logits = hid0 @ w1 + b1  (into sA)
    gemm256(sHid, w1, b1, sA, warp, lane, false);
    __syncthreads();

    // phase 4: masked CE, warp-cooperative per token
    float local = 0.f;
    for (int jj = 0; jj < 8; jj++) {
        int tkl = warp*8 + jj;
        int tok = tok0 + tkl;
        float v[8];
        #pragma unroll
        for (int i = 0; i < 8; i++) v[i] = sA[tkl*256 + lane*8 + i];
        float m = v[0];
        #pragma unroll
        for (int i = 1; i < 8; i++) m = fmaxf(m, v[i]);
        #pragma unroll
        for (int off = 16; off; off >>= 1) m = fmaxf(m, __shfl_xor_sync(0xffffffffu, m, off));
        float s = 0.f;
        #pragma unroll
        for (int i = 0; i < 8; i++) s += expf(v[i] - m);
        #pragma unroll
        for (int off = 16; off; off >>= 1) s += __shfl_xor_sync(0xffffffffu, s, off);
        if (lane == 0) {
            int t = tok & (NT-1);
            int b = tok >> 13;
            if (t < lens[b]) {
                int lab = wf[tok];
                local += m + logf(s) - sA[tkl*256 + lab];
            }
        }
    }
    if (lane == 0) atomicAdd(&g_num, local);
}

__global__ void finalize_kernel(const int* __restrict__ lens, float* __restrict__ out) {
    float denom = 0.f;
    for (int b = 0; b < NB; b++) denom += (float)lens[b];
    out[0] = g_num / fmaxf(denom, 1.f);
}

// ---------------- launcher ---------------------------------------------------
extern "C" void kernel_launch(void* const* d_in, const int* in_sizes, int n_in,
                              void* d_out, int out_size)
{
    const int*   wf     = (const int*)d_in[0];
    const int*   lens   = (const int*)d_in[1];
    const float* emb    = (const float*)d_in[2];
    const float* conv_w = (const float*)d_in[3];
    const float* conv_b = (const float*)d_in[4];
    const float* res_w  = (const float*)d_in[5];
    const float* res_b  = (const float*)d_in[6];
    const float* skip_w = (const float*)d_in[7];
    const float* skip_b = (const float*)d_in[8];
    const float* w0     = (const float*)d_in[9];
    const float* b0     = (const float*)d_in[10];
    const float* w1     = (const float*)d_in[11];
    const float* b1     = (const float*)d_in[12];

    static const int dil[NL] = {1,2,4,8,16,32,64,128,256,512,
                                1,2,4,8,16,32,64,128,256,512,
                                1,2,4,8,16,32,64,128,256,512};

    const int LAYER_SMEM = (KC*KC + KC*64 + NC*NC + 64*KC + 64*NC) * (int)sizeof(float); // 160 KB
    const int HEAD_SMEM  = 2*64*256 * (int)sizeof(float);                                 // 128 KB
    cudaFuncSetAttribute(layer_kernel, cudaFuncAttributeMaxDynamicSharedMemorySize, LAYER_SMEM);
    cudaFuncSetAttribute(head_kernel,  cudaFuncAttributeMaxDynamicSharedMemorySize, HEAD_SMEM);

    prep_kernel<<<1, NS>>>(skip_b);
    embed_kernel<<<NTOK/4, 256>>>(wf, emb);
    for (int i = 0; i < NL; i++)
        layer_kernel<<<NTOK/64, 256, LAYER_SMEM>>>(conv_w, conv_b, res_w, res_b,
                                                   i, dil[i], i & 1);
    head_kernel<<<NTOK/64, 256, HEAD_SMEM>>>(skip_w, w0, b0, w1, b1, wf, lens);
    finalize_kernel<<<1, 1>>>(lens, (float*)d_out);
}